// round 8
// baseline (speedup 1.0000x reference)
#include <cuda_runtime.h>
#include <math.h>

#define D 256
#define MAX_N 65536
#define EXP_CUT (-87.0f)
#define CAP 16384
#define SCAP 1024
#define ENC_NEG_INF 0x007FFFFFu
#define VB 64      // v-partial blocks
#define ZB 512     // zero blocks

// Persistent device scratch (statics give first-call init; K_B tail self-resets).
__device__ float        g_v[D];
__device__ float        g_vp[VB][D];
__device__ float        g_p[MAX_N];
__device__ unsigned int g_max_enc = ENC_NEG_INF;
__device__ int          g_nsurv   = 0;
__device__ int          g_done0   = 0;   // v-partial election
__device__ int          g_done1   = 0;   // score-kernel election
__device__ int          g_vflag   = 0;   // v-ready release flag
__device__ int          g_surv[CAP];
__device__ float        g_sval[CAP];

__device__ __forceinline__ unsigned int enc_f(float f) {
    unsigned int u = __float_as_uint(f);
    return (u & 0x80000000u) ? ~u : (u | 0x80000000u);
}
__device__ __forceinline__ float dec_f(unsigned int u) {
    return __uint_as_float((u & 0x80000000u) ? (u & 0x7FFFFFFFu) : ~u);
}
__device__ __forceinline__ float lrelu(float s) { return s > 0.f ? s : 0.2f * s; }

// K_A: fused v-compute + out-zeroing + p-compute.
//  bids [0,VB)        : v partials (wave-1 resident => spinners can't deadlock)
//  bids [VB,VB+ZB)    : zero `out`
//  bids [VB+ZB, ...)  : p[n] = x[n].v  (x loaded before the flag spin)
__global__ void __launch_bounds__(256) k_pre(
        const float* __restrict__ W, const float* __restrict__ a,
        const float* __restrict__ x, float* __restrict__ out,
        int N, int n_out4) {
    int bid = blockIdx.x;

    if (bid < VB) {
        int i  = threadIdx.x;
        int o0 = bid * 4;
        float a0 = __ldg(a + o0),     a1 = __ldg(a + o0 + 1);
        float a2 = __ldg(a + o0 + 2), a3 = __ldg(a + o0 + 3);
        float w0 = __ldg(W + (o0 + 0) * D + i);
        float w1 = __ldg(W + (o0 + 1) * D + i);
        float w2 = __ldg(W + (o0 + 2) * D + i);
        float w3 = __ldg(W + (o0 + 3) * D + i);
        g_vp[bid][i] = (a0 * w0 + a1 * w1) + (a2 * w2 + a3 * w3);

        __threadfence();
        __shared__ int s_last;
        if (threadIdx.x == 0) s_last = (atomicAdd(&g_done0, 1) == VB - 1);
        __syncthreads();
        if (!s_last) return;

        float s = 0.f;
        #pragma unroll 16
        for (int k = 0; k < VB; ++k) s += g_vp[k][i];
        g_v[i] = s;
        __threadfence();
        if (threadIdx.x == 0) atomicExch(&g_vflag, 1);   // release
        return;
    }
    bid -= VB;

    if (bid < ZB) {
        float4* o4 = (float4*)out;
        const float4 z = make_float4(0.f, 0.f, 0.f, 0.f);
        int tid  = bid * blockDim.x + threadIdx.x;
        int nthr = ZB * blockDim.x;
        for (int i = tid; i < n_out4; i += nthr) o4[i] = z;
        return;
    }
    bid -= ZB;

    int w = bid * 8 + (threadIdx.x >> 5);
    if (w >= N) return;
    int lane = threadIdx.x & 31;

    // Issue x loads FIRST (independent of v) — they fly while we spin.
    const float4* xr = (const float4*)(x + (size_t)w * D);
    float4 x0 = xr[lane], x1 = xr[lane + 32];

    // Acquire v.
    while (*(volatile int*)&g_vflag == 0) __nanosleep(64);
    asm volatile("" ::: "memory");
    __threadfence();

    const float4* vr = (const float4*)g_v;
    float4 v0 = vr[lane], v1 = vr[lane + 32];
    float s = x0.x*v0.x + x0.y*v0.y + x0.z*v0.z + x0.w*v0.w
            + x1.x*v1.x + x1.y*v1.y + x1.z*v1.z + x1.w*v1.w;
    #pragma unroll
    for (int o = 16; o; o >>= 1) s += __shfl_xor_sync(0xffffffffu, s, o);
    if (lane == 0) g_p[w] = s;
}

// K_B: score 4 edges/thread + global max + candidate-collect; last block finishes.
__global__ void __launch_bounds__(256) k_score(
        const int* __restrict__ src, const int* __restrict__ dst,
        int E, const float* __restrict__ x, float* __restrict__ out) {
    {
        int i4   = blockIdx.x * blockDim.x + threadIdx.x;
        int base = i4 * 4;
        float sc0 = -INFINITY, sc1 = -INFINITY, sc2 = -INFINITY, sc3 = -INFINITY;
        if (base + 3 < E) {
            int4 s4 = ((const int4*)src)[i4];
            int4 d4 = ((const int4*)dst)[i4];
            float ps0 = g_p[s4.x], ps1 = g_p[s4.y], ps2 = g_p[s4.z], ps3 = g_p[s4.w];
            float pd0 = g_p[d4.x], pd1 = g_p[d4.y], pd2 = g_p[d4.z], pd3 = g_p[d4.w];
            sc0 = lrelu(ps0 + pd0);
            sc1 = lrelu(ps1 + pd1);
            sc2 = lrelu(ps2 + pd2);
            sc3 = lrelu(ps3 + pd3);
        } else if (base < E) {
            if (base + 0 < E) sc0 = lrelu(g_p[src[base + 0]] + g_p[dst[base + 0]]);
            if (base + 1 < E) sc1 = lrelu(g_p[src[base + 1]] + g_p[dst[base + 1]]);
            if (base + 2 < E) sc2 = lrelu(g_p[src[base + 2]] + g_p[dst[base + 2]]);
        }
        float m = fmaxf(fmaxf(sc0, sc1), fmaxf(sc2, sc3));

        #pragma unroll
        for (int o = 16; o; o >>= 1) m = fmaxf(m, __shfl_xor_sync(0xffffffffu, m, o));
        __shared__ float sm[8];
        __shared__ unsigned int s_gmax;
        int lane = threadIdx.x & 31, wid = threadIdx.x >> 5;
        if (lane == 0) sm[wid] = m;
        __syncthreads();
        if (wid == 0 && lane == 0) {
            float bm = sm[0];
            #pragma unroll
            for (int k = 1; k < 8; ++k) bm = fmaxf(bm, sm[k]);
            unsigned int e = enc_f(bm);
            unsigned int old = atomicMax(&g_max_enc, e);
            s_gmax = old > e ? old : e;
        }
        __syncthreads();

        float thr = dec_f(s_gmax) + EXP_CUT;
        if (fmaxf(fmaxf(sc0, sc1), fmaxf(sc2, sc3)) > thr) {
            if (sc0 > thr) { int p = atomicAdd(&g_nsurv, 1); if (p < CAP) { g_surv[p] = base;     g_sval[p] = sc0; } }
            if (sc1 > thr) { int p = atomicAdd(&g_nsurv, 1); if (p < CAP) { g_surv[p] = base + 1; g_sval[p] = sc1; } }
            if (sc2 > thr) { int p = atomicAdd(&g_nsurv, 1); if (p < CAP) { g_surv[p] = base + 2; g_sval[p] = sc2; } }
            if (sc3 > thr) { int p = atomicAdd(&g_nsurv, 1); if (p < CAP) { g_surv[p] = base + 3; g_sval[p] = sc3; } }
        }
    }

    // ---- last-block election ----
    __threadfence();
    __shared__ int s_last;
    if (threadIdx.x == 0) s_last = (atomicAdd(&g_done1, 1) == (int)gridDim.x - 1);
    __syncthreads();
    if (!s_last) return;

    // ---- finish: filter vs final max, sumexp, scatter ----
    __shared__ int   s_sid[SCAP];
    __shared__ float s_sw[SCAP];
    __shared__ int   s_cnt;
    __shared__ float s_red2[8];
    __shared__ float s_sum;

    int n = g_nsurv; if (n > CAP) n = CAP;
    float gmax = dec_f(g_max_enc);
    if (threadIdx.x == 0) s_cnt = 0;
    __syncthreads();

    float part = 0.f;
    for (int k = threadIdx.x; k < n; k += blockDim.x) {
        float z = g_sval[k] - gmax;
        if (z > EXP_CUT) {
            float ex = __expf(z);
            part += ex;
            int p = atomicAdd(&s_cnt, 1);
            if (p < SCAP) { s_sid[p] = g_surv[k]; s_sw[p] = ex; }
        }
    }
    #pragma unroll
    for (int o = 16; o; o >>= 1) part += __shfl_xor_sync(0xffffffffu, part, o);
    int lane = threadIdx.x & 31, wid = threadIdx.x >> 5;
    if (lane == 0) s_red2[wid] = part;
    __syncthreads();
    if (wid == 0) {
        part = (lane < (int)(blockDim.x >> 5)) ? s_red2[lane] : 0.f;
        #pragma unroll
        for (int o = 16; o; o >>= 1) part += __shfl_xor_sync(0xffffffffu, part, o);
        if (lane == 0) s_sum = part;
    }
    __syncthreads();

    int   ns      = s_cnt < SCAP ? s_cnt : SCAP;
    float inv_sum = 1.f / s_sum;

    int warp = threadIdx.x >> 5, nwarps = blockDim.x >> 5;
    for (int k = warp; k < ns; k += nwarps) {
        float wgt = s_sw[k] * inv_sum;
        int e  = s_sid[k];
        int si = src[e], di = dst[e];

        const float4* xi = (const float4*)(x + (size_t)si * D);
        const float4* xj = (const float4*)(x + (size_t)di * D);
        float4 a0 = xi[lane], a1 = xi[lane + 32];
        float4 b0 = xj[lane], b1 = xj[lane + 32];
        float t, d2 = 0.f;
        t = a0.x - b0.x; d2 += t * t;
        t = a0.y - b0.y; d2 += t * t;
        t = a0.z - b0.z; d2 += t * t;
        t = a0.w - b0.w; d2 += t * t;
        t = a1.x - b1.x; d2 += t * t;
        t = a1.y - b1.y; d2 += t * t;
        t = a1.z - b1.z; d2 += t * t;
        t = a1.w - b1.w; d2 += t * t;
        #pragma unroll
        for (int o = 16; o; o >>= 1) d2 += __shfl_xor_sync(0xffffffffu, d2, o);

        float c = wgt * sqrtf(d2);
        float* op = out + (size_t)si * D;
        asm volatile("red.global.add.v4.f32 [%0], {%1,%2,%3,%4};" ::
            "l"(op + lane * 4), "f"(c * b0.x), "f"(c * b0.y), "f"(c * b0.z), "f"(c * b0.w)
            : "memory");
        asm volatile("red.global.add.v4.f32 [%0], {%1,%2,%3,%4};" ::
            "l"(op + (lane + 32) * 4), "f"(c * b1.x), "f"(c * b1.y), "f"(c * b1.z), "f"(c * b1.w)
            : "memory");
    }

    // ---- self-reset for graph replay ----
    __syncthreads();
    if (threadIdx.x == 0) {
        g_max_enc = ENC_NEG_INF;
        g_nsurv   = 0;
        g_done1   = 0;
        g_done0   = 0;
        g_vflag   = 0;
    }
}

extern "C" void kernel_launch(void* const* d_in, const int* in_sizes, int n_in,
                              void* d_out, int out_size) {
    const float* x  = (const float*)d_in[0];
    const int*   ei = (const int*)  d_in[1];
    const float* W  = (const float*)d_in[2];
    const float* a  = (const float*)d_in[3];
    float* out = (float*)d_out;

    int N = in_sizes[0] / D;
    int E = in_sizes[1] / 2;
    const int* src = ei;
    const int* dst = ei + E;

    int p_blocks     = (N * 32 + 255) / 256;
    int e4           = (E + 3) / 4;
    int score_blocks = (e4 + 255) / 256;
    int n_out4       = out_size / 4;

    k_pre<<<VB + ZB + p_blocks, 256>>>(W, a, x, out, N, n_out4);
    k_score<<<score_blocks, 256>>>(src, dst, E, x, out);
}

// round 9
// speedup vs baseline: 1.7199x; 1.7199x over previous
#include <cuda_runtime.h>
#include <math.h>

#define D 256
#define MAX_N 65536
#define EXP_CUT (-87.0f)
#define CAP 16384
#define SCAP 1024
#define ENC_NEG_INF 0x007FFFFFu
#define VB 32      // k_init blocks (8 W-rows each)

// Persistent device scratch (statics give first-call init; score tail self-resets).
__device__ float        g_v[D];          // zero-init; accumulated by k_init, reset by tail
__device__ float        g_p[MAX_N];
__device__ unsigned int g_max_enc = ENC_NEG_INF;
__device__ int          g_nsurv   = 0;
__device__ int          g_done1   = 0;
__device__ int          g_surv[CAP];
__device__ float        g_sval[CAP];

__device__ __forceinline__ unsigned int enc_f(float f) {
    unsigned int u = __float_as_uint(f);
    return (u & 0x80000000u) ? ~u : (u | 0x80000000u);
}
__device__ __forceinline__ float dec_f(unsigned int u) {
    return __uint_as_float((u & 0x80000000u) ? (u & 0x7FFFFFFFu) : ~u);
}
__device__ __forceinline__ float lrelu(float s) { return s > 0.f ? s : 0.2f * s; }

// K0: 32 blocks x 256 threads; block b accumulates 8 W-rows into g_v via atomicAdd.
// g_v is zero on entry (static init on first call; score-tail reset on replays).
__global__ void __launch_bounds__(256) k_init(const float* __restrict__ W,
                                              const float* __restrict__ a) {
    int i  = threadIdx.x;
    int o0 = blockIdx.x * 8;
    float s = 0.f;
    #pragma unroll
    for (int k = 0; k < 8; ++k)
        s = fmaf(__ldg(a + o0 + k), __ldg(W + (o0 + k) * D + i), s);
    atomicAdd(&g_v[i], s);
}

// K1: one warp per node — p[n] = x[n] . v.
__global__ void __launch_bounds__(256) k_dot(const float* __restrict__ x, int N) {
    int w = (blockIdx.x * blockDim.x + threadIdx.x) >> 5;
    if (w >= N) return;
    int lane = threadIdx.x & 31;
    const float4* xr = (const float4*)(x + (size_t)w * D);
    const float4* vr = (const float4*)g_v;
    float4 x0 = xr[lane], x1 = xr[lane + 32];
    float4 v0 = vr[lane], v1 = vr[lane + 32];
    float s = x0.x*v0.x + x0.y*v0.y + x0.z*v0.z + x0.w*v0.w
            + x1.x*v1.x + x1.y*v1.y + x1.z*v1.z + x1.w*v1.w;
    #pragma unroll
    for (int o = 16; o; o >>= 1) s += __shfl_xor_sync(0xffffffffu, s, o);
    if (lane == 0) g_p[w] = s;
}

// K2: fused mega-kernel.
//  blocks [0, ZB)   : zero `out` (overlaps with latency-bound score blocks)
//  blocks [ZB, ...) : 8 edges/thread — score, global max, candidate-collect
//  LAST block       : filter vs final max, sumexp, scatter, self-reset
__global__ void __launch_bounds__(256) k_score_zero(
        const int* __restrict__ src, const int* __restrict__ dst,
        int E, const float* __restrict__ x,
        float* __restrict__ out, int n_out4, int ZB) {
    if (blockIdx.x < (unsigned)ZB) {
        float4* o4 = (float4*)out;
        const float4 z = make_float4(0.f, 0.f, 0.f, 0.f);
        int tid  = blockIdx.x * blockDim.x + threadIdx.x;
        int nthr = ZB * blockDim.x;
        for (int i = tid; i < n_out4; i += nthr) o4[i] = z;
    } else {
        int t    = (blockIdx.x - ZB) * blockDim.x + threadIdx.x;
        int base = t * 8;
        float sc[8];
        #pragma unroll
        for (int k = 0; k < 8; ++k) sc[k] = -INFINITY;

        if (base + 7 < E) {
            int4 sa = ((const int4*)src)[t * 2];
            int4 sb = ((const int4*)src)[t * 2 + 1];
            int4 da = ((const int4*)dst)[t * 2];
            int4 db = ((const int4*)dst)[t * 2 + 1];
            // 16 independent gathers in flight.
            float p0 = g_p[sa.x], p1 = g_p[sa.y], p2 = g_p[sa.z], p3 = g_p[sa.w];
            float p4 = g_p[sb.x], p5 = g_p[sb.y], p6 = g_p[sb.z], p7 = g_p[sb.w];
            float q0 = g_p[da.x], q1 = g_p[da.y], q2 = g_p[da.z], q3 = g_p[da.w];
            float q4 = g_p[db.x], q5 = g_p[db.y], q6 = g_p[db.z], q7 = g_p[db.w];
            sc[0] = lrelu(p0 + q0); sc[1] = lrelu(p1 + q1);
            sc[2] = lrelu(p2 + q2); sc[3] = lrelu(p3 + q3);
            sc[4] = lrelu(p4 + q4); sc[5] = lrelu(p5 + q5);
            sc[6] = lrelu(p6 + q6); sc[7] = lrelu(p7 + q7);
        } else if (base < E) {
            for (int k = 0; base + k < E && k < 8; ++k)
                sc[k] = lrelu(g_p[src[base + k]] + g_p[dst[base + k]]);
        }
        float m = sc[0];
        #pragma unroll
        for (int k = 1; k < 8; ++k) m = fmaxf(m, sc[k]);

        #pragma unroll
        for (int o = 16; o; o >>= 1) m = fmaxf(m, __shfl_xor_sync(0xffffffffu, m, o));
        __shared__ float sm[8];
        __shared__ unsigned int s_gmax;
        int lane = threadIdx.x & 31, wid = threadIdx.x >> 5;
        if (lane == 0) sm[wid] = m;
        __syncthreads();
        if (wid == 0 && lane == 0) {
            float bm = sm[0];
            #pragma unroll
            for (int k = 1; k < 8; ++k) bm = fmaxf(bm, sm[k]);
            unsigned int e = enc_f(bm);
            unsigned int old = atomicMax(&g_max_enc, e);
            s_gmax = old > e ? old : e;   // running estimate, monotone <= final
        }
        __syncthreads();

        // Conservative candidate collection (superset of nonzero-weight edges).
        float thr = dec_f(s_gmax) + EXP_CUT;
        float mm = sc[0];
        #pragma unroll
        for (int k = 1; k < 8; ++k) mm = fmaxf(mm, sc[k]);
        if (mm > thr) {
            #pragma unroll
            for (int k = 0; k < 8; ++k) {
                if (sc[k] > thr) {
                    int p = atomicAdd(&g_nsurv, 1);
                    if (p < CAP) { g_surv[p] = base + k; g_sval[p] = sc[k]; }
                }
            }
        }
    }

    // ---- last-block election ----
    __threadfence();
    __shared__ int s_last;
    if (threadIdx.x == 0) s_last = (atomicAdd(&g_done1, 1) == (int)gridDim.x - 1);
    __syncthreads();
    if (!s_last) return;

    // ---- finish (exactly one block; all prior writes visible) ----
    __shared__ int   s_sid[SCAP];
    __shared__ float s_sw[SCAP];
    __shared__ int   s_cnt;
    __shared__ float s_red2[8];
    __shared__ float s_sum;

    int n = g_nsurv; if (n > CAP) n = CAP;
    float gmax = dec_f(g_max_enc);
    if (threadIdx.x == 0) s_cnt = 0;
    __syncthreads();

    float part = 0.f;
    for (int k = threadIdx.x; k < n; k += blockDim.x) {
        float z = g_sval[k] - gmax;
        if (z > EXP_CUT) {
            float ex = __expf(z);
            part += ex;
            int p = atomicAdd(&s_cnt, 1);
            if (p < SCAP) { s_sid[p] = g_surv[k]; s_sw[p] = ex; }
        }
    }
    #pragma unroll
    for (int o = 16; o; o >>= 1) part += __shfl_xor_sync(0xffffffffu, part, o);
    int lane = threadIdx.x & 31, wid = threadIdx.x >> 5;
    if (lane == 0) s_red2[wid] = part;
    __syncthreads();
    if (wid == 0) {
        part = (lane < (int)(blockDim.x >> 5)) ? s_red2[lane] : 0.f;
        #pragma unroll
        for (int o = 16; o; o >>= 1) part += __shfl_xor_sync(0xffffffffu, part, o);
        if (lane == 0) s_sum = part;
    }
    __syncthreads();

    int   ns      = s_cnt < SCAP ? s_cnt : SCAP;
    float inv_sum = 1.f / s_sum;

    int warp = threadIdx.x >> 5, nwarps = blockDim.x >> 5;
    for (int k = warp; k < ns; k += nwarps) {
        float wgt = s_sw[k] * inv_sum;
        int e  = s_sid[k];
        int si = src[e], di = dst[e];

        const float4* xi = (const float4*)(x + (size_t)si * D);
        const float4* xj = (const float4*)(x + (size_t)di * D);
        float4 a0 = xi[lane], a1 = xi[lane + 32];
        float4 b0 = xj[lane], b1 = xj[lane + 32];
        float t, d2 = 0.f;
        t = a0.x - b0.x; d2 += t * t;
        t = a0.y - b0.y; d2 += t * t;
        t = a0.z - b0.z; d2 += t * t;
        t = a0.w - b0.w; d2 += t * t;
        t = a1.x - b1.x; d2 += t * t;
        t = a1.y - b1.y; d2 += t * t;
        t = a1.z - b1.z; d2 += t * t;
        t = a1.w - b1.w; d2 += t * t;
        #pragma unroll
        for (int o = 16; o; o >>= 1) d2 += __shfl_xor_sync(0xffffffffu, d2, o);

        float c = wgt * sqrtf(d2);
        float* op = out + (size_t)si * D;
        asm volatile("red.global.add.v4.f32 [%0], {%1,%2,%3,%4};" ::
            "l"(op + lane * 4), "f"(c * b0.x), "f"(c * b0.y), "f"(c * b0.z), "f"(c * b0.w)
            : "memory");
        asm volatile("red.global.add.v4.f32 [%0], {%1,%2,%3,%4};" ::
            "l"(op + (lane + 32) * 4), "f"(c * b1.x), "f"(c * b1.y), "f"(c * b1.z), "f"(c * b1.w)
            : "memory");
    }

    // ---- self-reset for graph replay (incl. g_v for k_init's atomic accumulate) ----
    __syncthreads();
    g_v[threadIdx.x] = 0.f;   // blockDim == 256 == D
    if (threadIdx.x == 0) {
        g_max_enc = ENC_NEG_INF;
        g_nsurv   = 0;
        g_done1   = 0;
    }
}

extern "C" void kernel_launch(void* const* d_in, const int* in_sizes, int n_in,
                              void* d_out, int out_size) {
    const float* x  = (const float*)d_in[0];
    const int*   ei = (const int*)  d_in[1];
    const float* W  = (const float*)d_in[2];
    const float* a  = (const float*)d_in[3];
    float* out = (float*)d_out;

    int N = in_sizes[0] / D;
    int E = in_sizes[1] / 2;
    const int* src = ei;
    const int* dst = ei + E;

    int e8           = (E + 7) / 8;
    int score_blocks = (e8 + 255) / 256;
    const int ZB     = 512;
    int n_out4       = out_size / 4;

    k_init<<<VB, D>>>(W, a);
    k_dot<<<(N * 32 + 255) / 256, 256>>>(x, N);
    k_score_zero<<<score_blocks + ZB, 256>>>(src, dst, E, x, out, n_out4, ZB);
}